// round 5
// baseline (speedup 1.0000x reference)
#include <cuda_runtime.h>
#include <cstdint>
#include <cstddef>

#define VOCAB   50000
#define EMB     256
#define HID     512
#define NBATCH  256
#define T       512
#define NB      512
#define KTOT    768            // EMB + HID
#define GB_H    32
#define GB_B    4
#define NBLOCKS (GB_H * GB_B)  // 128
#define HS      16             // hid units per block -> 64 gate rows
#define BS      128            // batch rows per block
#define KC      16             // K chunk per buffer slot (16 k -> 32 dup floats/row)
#define NCHUNK  (KTOT / KC)    // 48
#define THREADS 512
#define NWARP   16
#define ROWF    (2 * KC)       // dup floats per row per chunk = 32
#define BUFW    (8 * ROWF)     // floats per (warp, buffer) slice = 256

// SMEM: weights 49152 floats (192KB) + staging 16*2*256 floats (32KB) = 229376 B
#define WS_FLOATS   (HS * KTOT * 4)
#define INS_FLOATS  (NWARP * 2 * BUFW)
#define SMEM_BYTES  ((WS_FLOATS + INS_FLOATS) * 4)

__device__ float     g_emb2[VOCAB * EMB * 2];   // duplicated embedding table (102.4 MB)
__device__ float     g_h[2][NB * HID * 2];      // duplicated hidden state, double-buffered
__device__ unsigned  g_cnt;
__device__ unsigned  g_gen;

__device__ __forceinline__ unsigned long long pack2(float lo, float hi) {
    unsigned long long r;
    asm("mov.b64 %0, {%1, %2};" : "=l"(r) : "f"(lo), "f"(hi));
    return r;
}
__device__ __forceinline__ float2 unpack2(unsigned long long v) {
    float lo, hi;
    asm("mov.b64 {%0, %1}, %2;" : "=f"(lo), "=f"(hi) : "l"(v));
    return make_float2(lo, hi);
}
__device__ __forceinline__ void ffma2(unsigned long long& acc,
                                      unsigned long long a, unsigned long long b) {
    asm("fma.rn.f32x2 %0, %1, %2, %0;" : "+l"(acc) : "l"(a), "l"(b));
}
__device__ __forceinline__ void cp16_ca(void* dst, const void* src) {
    unsigned d = (unsigned)__cvta_generic_to_shared(dst);
    asm volatile("cp.async.ca.shared.global [%0], [%1], 16;" :: "r"(d), "l"(src));
}
__device__ __forceinline__ void cp16_cg(void* dst, const void* src) {
    unsigned d = (unsigned)__cvta_generic_to_shared(dst);
    asm volatile("cp.async.cg.shared.global [%0], [%1], 16;" :: "r"(d), "l"(src));
}
__device__ __forceinline__ float sigf(float x) {
    return __fdividef(1.0f, 1.0f + __expf(-x));
}
__device__ __forceinline__ float tanhx(float x) {
    return __fmaf_rn(2.0f, sigf(2.0f * x), -1.0f);
}

__device__ __forceinline__ void grid_sync() {
    __syncthreads();
    if (threadIdx.x == 0) {
        volatile unsigned* genp = &g_gen;
        unsigned g = *genp;
        __threadfence();
        if (atomicAdd(&g_cnt, 1u) == NBLOCKS - 1) {
            g_cnt = 0;
            __threadfence();
            *genp = g + 1;
        } else {
            while (*genp == g) { __nanosleep(40); }
        }
    }
    __syncthreads();
}

__global__ void __launch_bounds__(THREADS, 1)
lstm_twin_kernel(const int* __restrict__ in1, const int* __restrict__ in2,
                 const float* __restrict__ emb, const float* __restrict__ Wih,
                 const float* __restrict__ Whh, const float* __restrict__ bih,
                 const float* __restrict__ bhh, const float* __restrict__ Wfc,
                 const float* __restrict__ bfc, float* __restrict__ out)
{
    extern __shared__ float smem[];
    float* Ws  = smem;
    float* ins = smem + WS_FLOATS;

    const int tid = threadIdx.x;
    const int bid = blockIdx.x;
    const int hg  = bid & (GB_H - 1);
    const int bg  = bid >> 5;
    const int w   = tid >> 5;            // warp 0..15
    const int lid = tid & 31;
    const int tbw = (tid >> 4) & 1;      // batch half within warp
    const int tj  = tid & 15;            // hid unit within tile
    const int jglob = hg * HS + tj;
    const int nbase = bg * BS;
    const int nb0   = nbase + 8 * w;     // this warp's first batch row
    const unsigned sw = (unsigned)(tj & 7);
    const int warpbase = w * 2 * BUFW;

    // ---- duplicate the embedding table: g_emb2[v][2k..2k+1] = emb[v][k] ----
    {
        const float4* src = (const float4*)emb;
        float4* dst = (float4*)g_emb2;
        const int total4 = VOCAB * EMB / 4;
        for (int i = bid * THREADS + tid; i < total4; i += NBLOCKS * THREADS) {
            float4 v = src[i];
            dst[2 * i + 0] = make_float4(v.x, v.x, v.y, v.y);
            dst[2 * i + 1] = make_float4(v.z, v.z, v.w, v.w);
        }
    }

    // ---- weight tile -> SMEM, Ws[tj][k][q] 16B cells, swizzled by tj&7 ----
    for (int r = 0; r < 4 * HS; r++) {
        int q   = r >> 4;
        int tjr = r & 15;
        int G   = q * HID + hg * HS + tjr;
        for (int k = tid; k < KTOT; k += THREADS) {
            float v = (k < EMB) ? Wih[G * EMB + k] : Whh[G * HID + (k - EMB)];
            unsigned cell = ((unsigned)(tjr * KTOT + k)) ^ ((unsigned)(tjr & 7));
            Ws[cell * 4 + q] = v;
        }
    }

    const unsigned long long bias01 =
        pack2(bih[0 * HID + jglob] + bhh[0 * HID + jglob],
              bih[1 * HID + jglob] + bhh[1 * HID + jglob]);
    const unsigned long long bias23 =
        pack2(bih[2 * HID + jglob] + bhh[2 * HID + jglob],
              bih[3 * HID + jglob] + bhh[3 * HID + jglob]);

    // zero h buffer 0 (duplicated layout)
    {
        float* hz = &g_h[0][0];
        int base = (bid * THREADS + tid) * 8;
#pragma unroll
        for (int i = 0; i < 8; i++) hz[base + i] = 0.0f;
    }
    grid_sync();

    // ---- warp-private staging: 64 cells (16B) per chunk, 2 per lane ----
    // cell s: row = (lid+32s)>>3 in 0..7, c = (lid)&7 cell column
    const int c8  = lid & 7;              // cell column 0..7 (covers 2 dup-k each)
    const int cf  = c8 * 4;               // float offset of cell within dup row
    const int r0  = lid >> 3;             // rows 0..3  (s=0)
    const int r1  = r0 + 4;               // rows 4..7  (s=1)
    const int d0  = r0 * ROWF + ((c8 ^ r0) << 2);   // swizzled dst offsets
    const int d1  = r1 * ROWF + ((c8 ^ r1) << 2);
    const int hrow0 = (nb0 + r0) * (2 * HID) + cf;
    const int hrow1 = (nb0 + r1) * (2 * HID) + cf;

    const int* tokarr = (bg < 2) ? in1 : in2;
    const int  rowb   = (nbase & (NBATCH - 1)) + 8 * w;
    const int* tp0 = tokarr + (size_t)(rowb + r0) * T;
    const int* tp1 = tokarr + (size_t)(rowb + r1) * T;

    int cur0 = __ldg(tp0);
    int cur1 = __ldg(tp1);

    float c[4];
#pragma unroll
    for (int b = 0; b < 4; b++) c[b] = 0.0f;

    const ulonglong2* Ws2 = (const ulonglong2*)Ws;

#pragma unroll 1
    for (int t = 0; t < T; t++) {
        const float* hread  = &g_h[t & 1][0];
        float*       hwrite = &g_h[(t + 1) & 1][0];

        // duplicated-embedding source rows for this step (cell-column offset baked in)
        const float* e2s0 = g_emb2 + (size_t)cur0 * (2 * EMB) + cf;
        const float* e2s1 = g_emb2 + (size_t)cur1 * (2 * EMB) + cf;

        // stage chunks 0 and 1 (all-embedding: k < 32 < EMB)
        {
            float* db0 = ins + warpbase;
            cp16_ca(db0 + d0, e2s0 + 0);
            cp16_ca(db0 + d1, e2s1 + 0);
            asm volatile("cp.async.commit_group;");
            float* db1 = ins + warpbase + BUFW;
            cp16_ca(db1 + d0, e2s0 + 2 * KC);
            cp16_ca(db1 + d1, e2s1 + 2 * KC);
            asm volatile("cp.async.commit_group;");
        }

        const int tn = (t + 1 < T) ? t + 1 : t;
        int nxt0 = __ldg(tp0 + tn);
        int nxt1 = __ldg(tp1 + tn);

        unsigned long long acc[4][2];
#pragma unroll
        for (int b = 0; b < 4; b++) { acc[b][0] = bias01; acc[b][1] = bias23; }

#pragma unroll 1
        for (int cch = 0; cch < NCHUNK; cch++) {
            if (cch == NCHUNK - 1) {
                asm volatile("cp.async.wait_group 0;");
            } else {
                asm volatile("cp.async.wait_group 1;");
            }

            const float* xb = ins + warpbase + (cch & 1) * BUFW;
            const int k0 = cch * KC;
#pragma unroll
            for (int kk = 0; kk < KC / 4; kk++) {
                const unsigned cb = (unsigned)(tj * KTOT + k0 + kk * 4);
                ulonglong2 w0 = Ws2[(cb + 0) ^ sw];
                ulonglong2 w1 = Ws2[(cb + 1) ^ sw];
                ulonglong2 w2 = Ws2[(cb + 2) ^ sw];
                ulonglong2 w3 = Ws2[(cb + 3) ^ sw];
#pragma unroll
                for (int b = 0; b < 4; b++) {
                    const int r = tbw * 4 + b;
                    // duplicated x: cells 2kk, 2kk+1 hold (x_{k0},x_{k0}),(x_{k1},x_{k1}),...
                    ulonglong2 xA = *(const ulonglong2*)(xb + r * ROWF + (((2 * kk + 0) ^ r) << 2));
                    ulonglong2 xB = *(const ulonglong2*)(xb + r * ROWF + (((2 * kk + 1) ^ r) << 2));
                    ffma2(acc[b][0], xA.x, w0.x); ffma2(acc[b][1], xA.x, w0.y);
                    ffma2(acc[b][0], xA.y, w1.x); ffma2(acc[b][1], xA.y, w1.y);
                    ffma2(acc[b][0], xB.x, w2.x); ffma2(acc[b][1], xB.x, w2.y);
                    ffma2(acc[b][0], xB.y, w3.x); ffma2(acc[b][1], xB.y, w3.y);
                }
            }

            // stage chunk cch+2 into the buffer just consumed
            if (cch + 2 < NCHUNK) {
                const int k0n = (cch + 2) * KC;
                float* dst = ins + warpbase + (cch & 1) * BUFW;
                if (k0n < EMB) {
                    cp16_ca(dst + d0, e2s0 + 2 * k0n);
                    cp16_ca(dst + d1, e2s1 + 2 * k0n);
                } else {
                    const int ho = 2 * (k0n - EMB);
                    cp16_cg(dst + d0, hread + hrow0 + ho);
                    cp16_cg(dst + d1, hread + hrow1 + ho);
                }
                asm volatile("cp.async.commit_group;");
            }
        }

        // pointwise LSTM cell; write h duplicated
#pragma unroll
        for (int b = 0; b < 4; b++) {
            float2 g01 = unpack2(acc[b][0]);
            float2 g23 = unpack2(acc[b][1]);
            float ig = sigf(g01.x);
            float fg = sigf(g01.y);
            float gg = tanhx(g23.x);
            float og = sigf(g23.y);
            c[b] = fg * c[b] + ig * gg;
            float hv = og * tanhx(c[b]);
            *(float2*)&hwrite[(size_t)(nb0 + tbw * 4 + b) * (2 * HID) + jglob * 2] =
                make_float2(hv, hv);
        }

        cur0 = nxt0;
        cur1 = nxt1;
        grid_sync();
    }

    // epilogue: h = h1*h2 -> FC(2) -> softmax (h stored duplicated, stride 2)
    if (bid == 0 && tid < NBATCH) {
        const int n = tid;
        const float* h1 = &g_h[0][(size_t)n * (2 * HID)];
        const float* h2 = &g_h[0][(size_t)(n + NBATCH) * (2 * HID)];
        float l0 = bfc[0], l1 = bfc[1];
#pragma unroll 4
        for (int j = 0; j < HID; j++) {
            float hp = __ldcg(&h1[j * 2]) * __ldcg(&h2[j * 2]);
            l0 = __fmaf_rn(hp, Wfc[j], l0);
            l1 = __fmaf_rn(hp, Wfc[HID + j], l1);
        }
        float m  = fmaxf(l0, l1);
        float e0 = __expf(l0 - m);
        float e1 = __expf(l1 - m);
        float s  = __fdividef(1.0f, e0 + e1);
        out[n * 2 + 0] = e0 * s;
        out[n * 2 + 1] = e1 * s;
    }
}

extern "C" void kernel_launch(void* const* d_in, const int* in_sizes, int n_in,
                              void* d_out, int out_size)
{
    (void)in_sizes; (void)n_in; (void)out_size;
    const int*   in1 = (const int*)d_in[0];
    const int*   in2 = (const int*)d_in[1];
    const float* emb = (const float*)d_in[2];
    const float* Wih = (const float*)d_in[3];
    const float* Whh = (const float*)d_in[4];
    const float* bih = (const float*)d_in[5];
    const float* bhh = (const float*)d_in[6];
    const float* Wfc = (const float*)d_in[7];
    const float* bfc = (const float*)d_in[8];
    float* out = (float*)d_out;

    cudaFuncSetAttribute(lstm_twin_kernel,
                         cudaFuncAttributeMaxDynamicSharedMemorySize, SMEM_BYTES);
    lstm_twin_kernel<<<NBLOCKS, THREADS, SMEM_BYTES>>>(
        in1, in2, emb, Wih, Whh, bih, bhh, Wfc, bfc, out);
}

// round 6
// speedup vs baseline: 1.3935x; 1.3935x over previous
#include <cuda_runtime.h>
#include <cstdint>
#include <cstddef>

#define VOCAB   50000
#define EMB     256
#define HID     512
#define NBATCH  256
#define T       512
#define NB      512
#define KTOT    768            // EMB + HID
#define GB_H    32
#define GB_B    4
#define NBLOCKS (GB_H * GB_B)  // 128
#define HS      16             // hid units per block -> 64 gate rows
#define BS      128            // batch rows per block
#define KSPLIT  2
#define KHALF   (KTOT / KSPLIT) // 384
#define KC      16             // K chunk per buffer slot
#define NCHUNK  (KHALF / KC)   // 24
#define THREADS 512
#define NWARP   16
#define RPW     16             // batch rows per warp
#define ROWF    KC             // floats per row per chunk = 16
#define BUFW    (RPW * ROWF)   // 256 floats per (warp,buffer)

// SMEM: weights 49152 floats (192KB) + staging 16*2*256 = 8192 floats (32KB) = 229376 B
#define WS_FLOATS   (HS * KTOT * 4)
#define INS_FLOATS  (NWARP * 2 * BUFW)
#define SMEM_BYTES  ((WS_FLOATS + INS_FLOATS) * 4)

__device__ float     g_h[2][NB * HID];
__device__ unsigned  g_cnt;
__device__ unsigned  g_gen;

__device__ __forceinline__ unsigned long long pack2(float lo, float hi) {
    unsigned long long r;
    asm("mov.b64 %0, {%1, %2};" : "=l"(r) : "f"(lo), "f"(hi));
    return r;
}
__device__ __forceinline__ float2 unpack2(unsigned long long v) {
    float lo, hi;
    asm("mov.b64 {%0, %1}, %2;" : "=f"(lo), "=f"(hi) : "l"(v));
    return make_float2(lo, hi);
}
__device__ __forceinline__ void ffma2(unsigned long long& acc,
                                      unsigned long long a, unsigned long long b) {
    asm("fma.rn.f32x2 %0, %1, %2, %0;" : "+l"(acc) : "l"(a), "l"(b));
}
__device__ __forceinline__ void fadd2(unsigned long long& a, unsigned long long b) {
    asm("add.rn.f32x2 %0, %0, %1;" : "+l"(a) : "l"(b));
}
__device__ __forceinline__ void cp16_ca(void* dst, const void* src) {
    unsigned d = (unsigned)__cvta_generic_to_shared(dst);
    asm volatile("cp.async.ca.shared.global [%0], [%1], 16;" :: "r"(d), "l"(src));
}
__device__ __forceinline__ void cp16_cg(void* dst, const void* src) {
    unsigned d = (unsigned)__cvta_generic_to_shared(dst);
    asm volatile("cp.async.cg.shared.global [%0], [%1], 16;" :: "r"(d), "l"(src));
}
__device__ __forceinline__ float sigf(float x) {
    return __fdividef(1.0f, 1.0f + __expf(-x));
}
__device__ __forceinline__ float tanhx(float x) {
    return __fmaf_rn(2.0f, sigf(2.0f * x), -1.0f);
}

__device__ __forceinline__ void grid_sync() {
    __syncthreads();
    if (threadIdx.x == 0) {
        volatile unsigned* genp = &g_gen;
        unsigned g = *genp;
        __threadfence();
        if (atomicAdd(&g_cnt, 1u) == NBLOCKS - 1) {
            g_cnt = 0;
            __threadfence();
            *genp = g + 1;
        } else {
            while (*genp == g) { __nanosleep(40); }
        }
    }
    __syncthreads();
}

__global__ void __launch_bounds__(THREADS, 1)
lstm_twin_kernel(const int* __restrict__ in1, const int* __restrict__ in2,
                 const float* __restrict__ emb, const float* __restrict__ Wih,
                 const float* __restrict__ Whh, const float* __restrict__ bih,
                 const float* __restrict__ bhh, const float* __restrict__ Wfc,
                 const float* __restrict__ bfc, float* __restrict__ out)
{
    extern __shared__ float smem[];
    float* Ws  = smem;
    float* ins = smem + WS_FLOATS;

    const int tid = threadIdx.x;
    const int bid = blockIdx.x;
    const int hg  = bid & (GB_H - 1);
    const int bg  = bid >> 5;
    const int w   = tid >> 5;            // warp 0..15
    const int lid = tid & 31;
    const int ks  = tid >> 8;            // k-split half 0/1
    const int wr  = w & 7;               // row-block within half
    const int tbw = (tid >> 4) & 1;      // row parity within warp
    const int tj  = tid & 15;            // hid unit within tile
    const int jglob = hg * HS + tj;
    const int nbase = bg * BS;
    const int nbw   = nbase + wr * RPW;  // warp's first batch row
    const int kbase = ks * KHALF;
    const unsigned sw = (unsigned)(tj & 7);
    const int warpbase = w * 2 * BUFW;

    // ---- weight tile -> SMEM, Ws[tj][k][q] 16B cells, swizzled by tj&7 ----
    for (int r = 0; r < 4 * HS; r++) {
        int q   = r >> 4;
        int tjr = r & 15;
        int G   = q * HID + hg * HS + tjr;
        for (int k = tid; k < KTOT; k += THREADS) {
            float v = (k < EMB) ? Wih[G * EMB + k] : Whh[G * HID + (k - EMB)];
            unsigned cell = ((unsigned)(tjr * KTOT + k)) ^ ((unsigned)(tjr & 7));
            Ws[cell * 4 + q] = v;
        }
    }

    // bias only on ks=0 half (partials added once)
    unsigned long long bias01 = 0ull, bias23 = 0ull;
    if (ks == 0) {
        bias01 = pack2(bih[0 * HID + jglob] + bhh[0 * HID + jglob],
                       bih[1 * HID + jglob] + bhh[1 * HID + jglob]);
        bias23 = pack2(bih[2 * HID + jglob] + bhh[2 * HID + jglob],
                       bih[3 * HID + jglob] + bhh[3 * HID + jglob]);
    }

    // zero h buffer 0
    {
        float* hz = &g_h[0][0];
        int base = (bid * THREADS + tid) * 4;
#pragma unroll
        for (int i = 0; i < 4; i++) hz[base + i] = 0.0f;
    }
    grid_sync();

    // ---- warp-private staging: 64 cells (16B) per chunk, 2 per lane ----
    const int sc  = lid & 3;              // cell column 0..3
    const int scf = sc * 4;               // float offset within row-chunk
    const int sr0 = lid >> 2;             // rows 0..7
    const int sr1 = sr0 + 8;              // rows 8..15
    const int d0  = sr0 * ROWF + ((sc ^ (sr0 & 3)) << 2);
    const int d1  = sr1 * ROWF + ((sc ^ (sr1 & 3)) << 2);
    const int gr0 = nbw + sr0;            // global batch rows staged by this lane
    const int gr1 = nbw + sr1;

    const int* tokarr = (bg < 2) ? in1 : in2;
    const int  rowb   = (nbase & (NBATCH - 1)) + wr * RPW;
    const int* tp0 = tokarr + (size_t)(rowb + sr0) * T;
    const int* tp1 = tokarr + (size_t)(rowb + sr1) * T;

    int cur0 = __ldg(tp0);
    int cur1 = __ldg(tp1);

    float c[8];
#pragma unroll
    for (int b = 0; b < 8; b++) c[b] = 0.0f;

    const ulonglong2* Ws2 = (const ulonglong2*)Ws;

#pragma unroll 1
    for (int t = 0; t < T; t++) {
        const float* hread  = &g_h[t & 1][0];
        float*       hwrite = &g_h[(t + 1) & 1][0];

        const float* e0 = emb + (size_t)cur0 * EMB + scf;
        const float* e1 = emb + (size_t)cur1 * EMB + scf;
        const float* h0 = hread + (size_t)gr0 * HID + scf - EMB;  // add kabs later
        const float* h1 = hread + (size_t)gr1 * HID + scf - EMB;

        // stage chunks 0 and 1
#pragma unroll
        for (int cc = 0; cc < 2; cc++) {
            const int kabs = kbase + cc * KC;
            float* dst = ins + warpbase + (cc & 1) * BUFW;
            if (kabs < EMB) {
                cp16_ca(dst + d0, e0 + kabs);
                cp16_ca(dst + d1, e1 + kabs);
            } else {
                cp16_cg(dst + d0, h0 + kabs);
                cp16_cg(dst + d1, h1 + kabs);
            }
            asm volatile("cp.async.commit_group;");
        }

        // prefetch next step's tokens
        const int tn = (t + 1 < T) ? t + 1 : t;
        int nxt0 = __ldg(tp0 + tn);
        int nxt1 = __ldg(tp1 + tn);

        unsigned long long acc[8][2];
#pragma unroll
        for (int b = 0; b < 8; b++) { acc[b][0] = bias01; acc[b][1] = bias23; }

#pragma unroll 1
        for (int cch = 0; cch < NCHUNK; cch++) {
            if (cch == NCHUNK - 1) {
                asm volatile("cp.async.wait_group 0;");
            } else {
                asm volatile("cp.async.wait_group 1;");
            }

            const float* xb = ins + warpbase + (cch & 1) * BUFW;
#pragma unroll
            for (int kk = 0; kk < KC / 4; kk++) {
                const unsigned cb = (unsigned)(tj * KTOT + kbase + cch * KC + kk * 4);
                ulonglong2 w0 = Ws2[(cb + 0) ^ sw];
                ulonglong2 w1 = Ws2[(cb + 1) ^ sw];
                ulonglong2 w2 = Ws2[(cb + 2) ^ sw];
                ulonglong2 w3 = Ws2[(cb + 3) ^ sw];
#pragma unroll
                for (int b = 0; b < 8; b++) {
                    const int r = 2 * b + tbw;   // interleaved rows: wavefront-friendly
                    float4 x = *(const float4*)(xb + r * ROWF + ((kk ^ (r & 3)) << 2));
                    unsigned long long dd0 = pack2(x.x, x.x);
                    ffma2(acc[b][0], dd0, w0.x); ffma2(acc[b][1], dd0, w0.y);
                    unsigned long long dd1 = pack2(x.y, x.y);
                    ffma2(acc[b][0], dd1, w1.x); ffma2(acc[b][1], dd1, w1.y);
                    unsigned long long dd2 = pack2(x.z, x.z);
                    ffma2(acc[b][0], dd2, w2.x); ffma2(acc[b][1], dd2, w2.y);
                    unsigned long long dd3 = pack2(x.w, x.w);
                    ffma2(acc[b][0], dd3, w3.x); ffma2(acc[b][1], dd3, w3.y);
                }
            }

            // stage chunk cch+2 into the buffer just consumed
            if (cch + 2 < NCHUNK) {
                const int kabs = kbase + (cch + 2) * KC;
                float* dst = ins + warpbase + (cch & 1) * BUFW;
                if (kabs < EMB) {
                    cp16_ca(dst + d0, e0 + kabs);
                    cp16_ca(dst + d1, e1 + kabs);
                } else {
                    cp16_cg(dst + d0, h0 + kabs);
                    cp16_cg(dst + d1, h1 + kabs);
                }
                asm volatile("cp.async.commit_group;");
            }
        }

        // ---- cross-half reduction via SMEM (coalesced layout [b][thread]) ----
        __syncthreads();                     // all staging reads done; ins reusable
        if (ks) {
            const int col = tid & 255;
#pragma unroll
            for (int b = 0; b < 8; b++) {
                *(ulonglong2*)(ins + b * 1024 + col * 4) =
                    make_ulonglong2(acc[b][0], acc[b][1]);
            }
        }
        __syncthreads();
        if (!ks) {
#pragma unroll
            for (int b = 0; b < 8; b++) {
                ulonglong2 p = *(const ulonglong2*)(ins + b * 1024 + tid * 4);
                fadd2(acc[b][0], p.x);
                fadd2(acc[b][1], p.y);
                float2 g01 = unpack2(acc[b][0]);
                float2 g23 = unpack2(acc[b][1]);
                float ig = sigf(g01.x);
                float fg = sigf(g01.y);
                float gg = tanhx(g23.x);
                float og = sigf(g23.y);
                c[b] = fg * c[b] + ig * gg;
                float hv = og * tanhx(c[b]);
                hwrite[(size_t)(nbw + 2 * b + tbw) * HID + jglob] = hv;
            }
        }

        cur0 = nxt0;
        cur1 = nxt1;
        grid_sync();
    }

    // epilogue: h = h1*h2 -> FC(2) -> softmax
    if (bid == 0 && tid < NBATCH) {
        const int n = tid;
        const float* h1 = &g_h[0][(size_t)n * HID];
        const float* h2 = &g_h[0][(size_t)(n + NBATCH) * HID];
        float l0 = bfc[0], l1 = bfc[1];
#pragma unroll 4
        for (int j = 0; j < HID; j++) {
            float hp = __ldcg(&h1[j]) * __ldcg(&h2[j]);
            l0 = __fmaf_rn(hp, Wfc[j], l0);
            l1 = __fmaf_rn(hp, Wfc[HID + j], l1);
        }
        float m  = fmaxf(l0, l1);
        float e0 = __expf(l0 - m);
        float e1 = __expf(l1 - m);
        float s  = __fdividef(1.0f, e0 + e1);
        out[n * 2 + 0] = e0 * s;
        out[n * 2 + 1] = e1 * s;
    }
}

extern "C" void kernel_launch(void* const* d_in, const int* in_sizes, int n_in,
                              void* d_out, int out_size)
{
    (void)in_sizes; (void)n_in; (void)out_size;
    const int*   in1 = (const int*)d_in[0];
    const int*   in2 = (const int*)d_in[1];
    const float* emb = (const float*)d_in[2];
    const float* Wih = (const float*)d_in[3];
    const float* Whh = (const float*)d_in[4];
    const float* bih = (const float*)d_in[5];
    const float* bhh = (const float*)d_in[6];
    const float* Wfc = (const float*)d_in[7];
    const float* bfc = (const float*)d_in[8];
    float* out = (float*)d_out;

    cudaFuncSetAttribute(lstm_twin_kernel,
                         cudaFuncAttributeMaxDynamicSharedMemorySize, SMEM_BYTES);
    lstm_twin_kernel<<<NBLOCKS, THREADS, SMEM_BYTES>>>(
        in1, in2, emb, Wih, Whh, bih, bhh, Wfc, bfc, out);
}